// round 15
// baseline (speedup 1.0000x reference)
#include <cuda_runtime.h>
#include <cuda_bf16.h>
#include <cstdint>

#define NN 20000
#define NE 100000

typedef unsigned long long ull;

__device__ float g_ebn[NE * 10];
__device__ float g_h1[NE * 16];
__device__ float g_h2[NE * 32];
__device__ float g_xbn[NN * 16];
__device__ float g_x1[NN * 32];
__device__ float g_x2[NN * 64];
__device__ float g_m1[NE * 64];            // edge-MLP layer1 activations
__device__ __nv_bfloat16 g_C1h[512 * 16];  // conv1 w2 bf16 hi, [n][k]
__device__ __nv_bfloat16 g_C1l[512 * 16];  // conv1 w2 bf16 lo
__device__ __nv_bfloat16 g_B2h[2048 * 32]; // conv2 w2 bf16 hi, [n][k]
__device__ __nv_bfloat16 g_B2l[2048 * 32]; // conv2 w2 bf16 lo
__device__ __nv_bfloat16 g_W1h[64 * 152];  // mlp_w1 bf16 hi, [n][k pad152]
__device__ __nv_bfloat16 g_W1l[64 * 152];  // mlp_w1 bf16 lo
__device__ double g_dsum[26], g_dss[26];
__device__ float g_emean[10], g_ers[10];
__device__ float g_xmean[16], g_xrs[16];

__device__ __forceinline__ float lrelu(float v) { return v > 0.f ? v : 0.1f * v; }

// ---- packed f32x2 helpers (k6b) ---------------------------------------------
__device__ __forceinline__ ull bcast2(float v) {
    ull r;
    unsigned u = __float_as_uint(v);
    asm("mov.b64 %0, {%1, %2};" : "=l"(r) : "r"(u), "r"(u));
    return r;
}
__device__ __forceinline__ ull fma2(ull a, ull b, ull c) {
    ull d;
    asm("fma.rn.f32x2 %0, %1, %2, %3;" : "=l"(d) : "l"(a), "l"(b), "l"(c));
    return d;
}
__device__ __forceinline__ float2 unpk2(ull v) {
    unsigned lo, hi;
    asm("mov.b64 {%0, %1}, %2;" : "=r"(lo), "=r"(hi) : "l"(v));
    return make_float2(__uint_as_float(lo), __uint_as_float(hi));
}

// ---- warp-level bf16 MMA ----------------------------------------------------
__device__ __forceinline__ void mma_bf16(float& c0, float& c1, float& c2, float& c3,
                                         uint32_t a0, uint32_t a1, uint32_t a2, uint32_t a3,
                                         uint32_t b0, uint32_t b1) {
    asm("mma.sync.aligned.m16n8k16.row.col.f32.bf16.bf16.f32 "
        "{%0,%1,%2,%3}, {%4,%5,%6,%7}, {%8,%9}, {%0,%1,%2,%3};"
        : "+f"(c0), "+f"(c1), "+f"(c2), "+f"(c3)
        : "r"(a0), "r"(a1), "r"(a2), "r"(a3), "r"(b0), "r"(b1));
}

// ---------------- BatchNorm statistics (coalesced) ---------------------------
__global__ void bn_init() {
    int t = threadIdx.x;
    if (t < 26) { g_dsum[t] = 0.0; g_dss[t] = 0.0; }
}

__global__ void bn_acc(const float* __restrict__ e, const float* __restrict__ x) {
    __shared__ double s_sh[320], ss_sh[320];
    int b = blockIdx.x, t = threadIdx.x;
    double s = 0.0, ss = 0.0;
    if (b < 40) {
        int base = b * 25000;
        for (int i = base + t; i < base + 25000; i += 320) {
            float f = e[i];
            s += (double)f; ss += (double)f * f;
        }
    } else {
        int base = (b - 40) * 20000;
        for (int i = base + t; i < base + 20000; i += 320) {
            float f = x[i];
            s += (double)f; ss += (double)f * f;
        }
    }
    s_sh[t] = s; ss_sh[t] = ss;
    __syncthreads();
    if (b < 40) {
        if (t < 10) {
            double a = 0.0, c = 0.0;
            for (int k = t; k < 320; k += 10) { a += s_sh[k]; c += ss_sh[k]; }
            atomicAdd(&g_dsum[t], a);
            atomicAdd(&g_dss[t], c);
        }
    } else {
        if (t < 16) {
            double a = 0.0, c = 0.0;
            for (int k = t; k < 320; k += 16) { a += s_sh[k]; c += ss_sh[k]; }
            atomicAdd(&g_dsum[10 + t], a);
            atomicAdd(&g_dss[10 + t], c);
        }
    }
}

__global__ void bn_fin() {
    int t = threadIdx.x;
    if (t < 10) {
        double m = g_dsum[t] / NE;
        double var = g_dss[t] / NE - m * m;
        g_emean[t] = (float)m;
        g_ers[t] = (float)(1.0 / sqrt(var + 1e-5));
    } else if (t < 26) {
        double m = g_dsum[t] / NN;
        double var = g_dss[t] / NN - m * m;
        g_xmean[t - 10] = (float)m;
        g_xrs[t - 10] = (float)(1.0 / sqrt(var + 1e-5));
    }
}

// ---------------- weight prep ------------------------------------------------
__global__ void prep_w(const float* __restrict__ w1g, const float* __restrict__ w2g,
                       const float* __restrict__ mw1) {
    int b = blockIdx.x;
    if (b < 32) {  // conv1: nn1_w2 [16,512] -> bf16 hi/lo [n512][k16]
        int idx = b * 256 + threadIdx.x;
        int n = idx >> 4, k = idx & 15;
        float f = w1g[k * 512 + n];
        __nv_bfloat16 bh = __float2bfloat16(f);
        g_C1h[idx] = bh;
        g_C1l[idx] = __float2bfloat16(f - __bfloat162float(bh));
    } else if (b < 288) {  // conv2: [k32][n2048] -> bf16 hi/lo [n][k]
        int idx = (b - 32) * 256 + threadIdx.x;
        int k = idx & 31, n = idx >> 5;
        float f = w2g[k * 2048 + n];
        __nv_bfloat16 bh = __float2bfloat16(f);
        __nv_bfloat16 bl = __float2bfloat16(f - __bfloat162float(bh));
        g_B2h[n * 32 + k] = bh;
        g_B2l[n * 32 + k] = bl;
    } else {  // mlp_w1 [138,64] -> bf16 hi/lo [n64][k152 pad-zero]
        int idx = (b - 288) * 256 + threadIdx.x;
        int n = idx / 152, k = idx - n * 152;
        float f = (k < 138) ? mw1[k * 64 + n] : 0.f;
        __nv_bfloat16 bh = __float2bfloat16(f);
        g_W1h[idx] = bh;
        g_W1l[idx] = __float2bfloat16(f - __bfloat162float(bh));
    }
}

// ---------------- K1: edge BN + h1 + h2 (coalesced staging) ------------------
__global__ void k1_edge(const float* __restrict__ e,
                        const float* __restrict__ eg, const float* __restrict__ eb,
                        const float* __restrict__ w1, const float* __restrict__ b1,
                        const float* __restrict__ w2, const float* __restrict__ b2) {
    __shared__ float sw1[160], sw2[320], sb1[16], sb2[32], sg[10], sb[10], sm[10], srs[10];
    __shared__ float in_sh[2560];
    int tid = threadIdx.x;
    int base = blockIdx.x * 2560;
    for (int i = tid; i < 160; i += 256) sw1[i] = w1[i];
    for (int i = tid; i < 320; i += 256) sw2[i] = w2[i];
    if (tid < 16) sb1[tid] = b1[tid];
    if (tid < 32) sb2[tid] = b2[tid];
    if (tid < 10) { sg[tid] = eg[tid]; sb[tid] = eb[tid]; sm[tid] = g_emean[tid]; srs[tid] = g_ers[tid]; }
    for (int i = tid; i < 2560; i += 256) {
        int gi = base + i;
        in_sh[i] = (gi < NE * 10) ? e[gi] : 0.f;
    }
    __syncthreads();
    int eid = blockIdx.x * 256 + tid;
    float ev[10];
    if (eid < NE) {
#pragma unroll
        for (int c = 0; c < 10; c++) {
            float f = (in_sh[tid * 10 + c] - sm[c]) * srs[c] * sg[c] + sb[c];
            ev[c] = f;
        }
#pragma unroll
        for (int o = 0; o < 16; o++) {
            float t = sb1[o];
#pragma unroll
            for (int c = 0; c < 10; c++) t += ev[c] * sw1[c * 16 + o];
            g_h1[eid * 16 + o] = lrelu(t);
        }
#pragma unroll
        for (int o = 0; o < 32; o++) {
            float t = sb2[o];
#pragma unroll
            for (int c = 0; c < 10; c++) t += ev[c] * sw2[c * 32 + o];
            g_h2[eid * 32 + o] = lrelu(t);
        }
    }
    __syncthreads();
    if (eid < NE) {
#pragma unroll
        for (int c = 0; c < 10; c++) in_sh[tid * 10 + c] = ev[c];
    }
    __syncthreads();
    for (int i = tid; i < 2560; i += 256) {
        int gi = base + i;
        if (gi < NE * 10) g_ebn[gi] = in_sh[i];
    }
}

// ---------------- K2: node BN + x1 = xbn @ l1_root + l1_bias -----------------
__global__ void k2_node(const float* __restrict__ x,
                        const float* __restrict__ ng, const float* __restrict__ nb,
                        const float* __restrict__ root, const float* __restrict__ bias) {
    __shared__ float sroot[512], sbias[32], sg[16], sb[16], sm[16], srs[16];
    int tid = threadIdx.x;
    for (int i = tid; i < 512; i += 256) sroot[i] = root[i];
    if (tid < 32) sbias[tid] = bias[tid];
    if (tid < 16) { sg[tid] = ng[tid]; sb[tid] = nb[tid]; sm[tid] = g_xmean[tid]; srs[tid] = g_xrs[tid]; }
    __syncthreads();
    int nid = blockIdx.x * 256 + tid;
    if (nid >= NN) return;
    float xv[16];
#pragma unroll
    for (int i = 0; i < 16; i++) {
        float f = (x[nid * 16 + i] - sm[i]) * srs[i] * sg[i] + sb[i];
        xv[i] = f;
        g_xbn[nid * 16 + i] = f;
    }
#pragma unroll
    for (int o = 0; o < 32; o++) {
        float t = sbias[o];
#pragma unroll
        for (int i = 0; i < 16; i++) t += xv[i] * sroot[i * 32 + o];
        g_x1[nid * 32 + o] = t;
    }
}

// ---------------- K3: NNConv1 via warp MMA (bf16 3-split) --------------------
__global__ __launch_bounds__(128) void k3_mma(const int* __restrict__ ei,
                                              const float* __restrict__ b2) {
    __shared__ __nv_bfloat16 Bh[512 * 16], Bl[512 * 16];
    __shared__ __nv_bfloat16 Ah[64 * 24], Al[64 * 24];
    __shared__ float x_sh[64 * 17];
    __shared__ float bias_sh[512];
    __shared__ int dst_sh[64];
    int tid = threadIdx.x;
    int lane = tid & 31, w = tid >> 5;
    int e0 = blockIdx.x * 64;

    {
        const uint4* sH = (const uint4*)g_C1h;
        const uint4* sL = (const uint4*)g_C1l;
        uint4* dH = (uint4*)Bh;
        uint4* dL = (uint4*)Bl;
        for (int i = tid; i < 1024; i += 128) { dH[i] = sH[i]; dL[i] = sL[i]; }
    }
    for (int i = tid; i < 512; i += 128) bias_sh[i] = b2[i];
    if (tid < 64) {
        int ge = e0 + tid;
        dst_sh[tid] = (ge < NE) ? ei[NE + ge] : 0;
    }
    for (int i = tid; i < 1024; i += 128) {
        int e = i >> 4, k = i & 15;
        int ge = e0 + e;
        float f = (ge < NE) ? g_h1[ge * 16 + k] : 0.f;
        __nv_bfloat16 bh = __float2bfloat16(f);
        Ah[e * 24 + k] = bh;
        Al[e * 24 + k] = __float2bfloat16(f - __bfloat162float(bh));
    }
    for (int i = tid; i < 1024; i += 128) {
        int e = i >> 4, ii = i & 15;
        int ge = e0 + e;
        x_sh[e * 17 + ii] = (ge < NE) ? g_xbn[ei[ge] * 16 + ii] : 0.f;
    }
    __syncthreads();

    int g = lane >> 2, m = lane & 3;
    int eA = w * 16 + g;
    uint32_t a0 = *(const uint32_t*)&Ah[eA * 24 + 2 * m];
    uint32_t a1 = *(const uint32_t*)&Ah[(eA + 8) * 24 + 2 * m];
    uint32_t a2 = *(const uint32_t*)&Ah[eA * 24 + 2 * m + 8];
    uint32_t a3 = *(const uint32_t*)&Ah[(eA + 8) * 24 + 2 * m + 8];
    uint32_t l0 = *(const uint32_t*)&Al[eA * 24 + 2 * m];
    uint32_t l1 = *(const uint32_t*)&Al[(eA + 8) * 24 + 2 * m];
    uint32_t l2 = *(const uint32_t*)&Al[eA * 24 + 2 * m + 8];
    uint32_t l3 = *(const uint32_t*)&Al[(eA + 8) * 24 + 2 * m + 8];

    float acc[16];
#pragma unroll
    for (int i = 0; i < 16; i++) acc[i] = 0.f;

#pragma unroll 4
    for (int ob = 0; ob < 64; ob++) {
        const __nv_bfloat16* bp = &Bh[(ob * 8 + g) * 16];
        const __nv_bfloat16* lp = &Bl[(ob * 8 + g) * 16];
        uint32_t b0 = *(const uint32_t*)&bp[2 * m];
        uint32_t b1 = *(const uint32_t*)&bp[2 * m + 8];
        uint32_t bl0 = *(const uint32_t*)&lp[2 * m];
        uint32_t bl1 = *(const uint32_t*)&lp[2 * m + 8];

        float c0 = 0.f, c1 = 0.f, c2 = 0.f, c3 = 0.f;
        mma_bf16(c0, c1, c2, c3, a0, a1, a2, a3, b0, b1);
        mma_bf16(c0, c1, c2, c3, l0, l1, l2, l3, b0, b1);
        mma_bf16(c0, c1, c2, c3, a0, a1, a2, a3, bl0, bl1);

        int iL = ob >> 2;
        float xa = x_sh[eA * 17 + iL];
        float xb = x_sh[(eA + 8) * 17 + iL];
        float bv0 = bias_sh[ob * 8 + 2 * m];
        float bv1 = bias_sh[ob * 8 + 2 * m + 1];
        int q = (ob & 3) * 2;
        acc[q]         = fmaf(xa, lrelu(c0 + bv0), acc[q]);
        acc[q + 1]     = fmaf(xa, lrelu(c1 + bv1), acc[q + 1]);
        acc[8 + q]     = fmaf(xb, lrelu(c2 + bv0), acc[8 + q]);
        acc[8 + q + 1] = fmaf(xb, lrelu(c3 + bv1), acc[8 + q + 1]);
    }

    int o0 = 2 * m;
    if (e0 + eA < NE) {
        int d = dst_sh[eA];
#pragma unroll
        for (int q = 0; q < 4; q++) {
            atomicAdd(&g_x1[d * 32 + q * 8 + o0], acc[q * 2]);
            atomicAdd(&g_x1[d * 32 + q * 8 + o0 + 1], acc[q * 2 + 1]);
        }
    }
    if (e0 + eA + 8 < NE) {
        int d = dst_sh[eA + 8];
#pragma unroll
        for (int q = 0; q < 4; q++) {
            atomicAdd(&g_x1[d * 32 + q * 8 + o0], acc[8 + q * 2]);
            atomicAdd(&g_x1[d * 32 + q * 8 + o0 + 1], acc[8 + q * 2 + 1]);
        }
    }
}

// ---------------- K4: x2 = x1 @ l2_root + l2_bias ----------------------------
__global__ void k4_node(const float* __restrict__ root, const float* __restrict__ bias) {
    __shared__ float sroot[2048], sbias[64];
    int tid = threadIdx.x;
    for (int i = tid; i < 2048; i += 256) sroot[i] = root[i];
    if (tid < 64) sbias[tid] = bias[tid];
    __syncthreads();
    int idx = blockIdx.x * 256 + tid;
    if (idx >= NN * 64) return;
    int n = idx >> 6, o = idx & 63;
    float t = sbias[o];
#pragma unroll
    for (int i = 0; i < 32; i++) t += g_x1[n * 32 + i] * sroot[i * 64 + o];
    g_x2[idx] = t;
}

// ---------------- K5: NNConv2 via warp MMA (bf16 3-split) --------------------
__global__ __launch_bounds__(128) void k5_conv2_mma(const int* __restrict__ ei,
                                                    const float* __restrict__ b2) {
    __shared__ __nv_bfloat16 Bh_sh[128 * 40];
    __shared__ __nv_bfloat16 Bl_sh[128 * 40];
    __shared__ __nv_bfloat16 Ah_sh[64 * 40];
    __shared__ __nv_bfloat16 Al_sh[64 * 40];
    __shared__ float x_sh[64 * 33];
    __shared__ float bias_sh[2048];
    __shared__ int dst_sh[64];
    int tid = threadIdx.x;
    int lane = tid & 31, w = tid >> 5;
    int e0 = blockIdx.x * 64;

    uint4 rH[4], rL[4];
    int n_ = tid >> 2, q_ = tid & 3;
    {
        const uint4* srcH = (const uint4*)(g_B2h);
        const uint4* srcL = (const uint4*)(g_B2l);
#pragma unroll
        for (int j = 0; j < 4; j++) {
            rH[j] = srcH[(n_ + 32 * j) * 4 + q_];
            rL[j] = srcL[(n_ + 32 * j) * 4 + q_];
        }
    }

    for (int i = tid; i < 2048; i += 128) {
        int e = i >> 5, k = i & 31;
        int ge = e0 + e;
        float f = (ge < NE) ? g_h2[ge * 32 + k] : 0.f;
        __nv_bfloat16 bh = __float2bfloat16(f);
        Ah_sh[e * 40 + k] = bh;
        Al_sh[e * 40 + k] = __float2bfloat16(f - __bfloat162float(bh));
    }
    for (int i = tid; i < 2048; i += 128) {
        int e = i >> 5, ii = i & 31;
        int ge = e0 + e;
        x_sh[e * 33 + ii] = (ge < NE) ? g_x1[ei[ge] * 32 + ii] : 0.f;
    }
    if (tid < 64) {
        int ge = e0 + tid;
        dst_sh[tid] = (ge < NE) ? ei[NE + ge] : 0;
    }
    for (int i = tid; i < 2048; i += 128) bias_sh[i] = b2[i];
    __syncthreads();

    int g = lane >> 2, m = lane & 3;
    int eA = w * 16 + g;
    uint32_t ah[2][4], al[2][4];
#pragma unroll
    for (int ks = 0; ks < 2; ks++) {
        int kb = ks * 16 + 2 * m;
        ah[ks][0] = *(const uint32_t*)&Ah_sh[eA * 40 + kb];
        ah[ks][1] = *(const uint32_t*)&Ah_sh[(eA + 8) * 40 + kb];
        ah[ks][2] = *(const uint32_t*)&Ah_sh[eA * 40 + kb + 8];
        ah[ks][3] = *(const uint32_t*)&Ah_sh[(eA + 8) * 40 + kb + 8];
        al[ks][0] = *(const uint32_t*)&Al_sh[eA * 40 + kb];
        al[ks][1] = *(const uint32_t*)&Al_sh[(eA + 8) * 40 + kb];
        al[ks][2] = *(const uint32_t*)&Al_sh[eA * 40 + kb + 8];
        al[ks][3] = *(const uint32_t*)&Al_sh[(eA + 8) * 40 + kb + 8];
    }

    float acc[32];
#pragma unroll
    for (int i = 0; i < 32; i++) acc[i] = 0.f;

    for (int c = 0; c < 16; c++) {
        if (c > 0) __syncthreads();
#pragma unroll
        for (int j = 0; j < 4; j++) {
            *((uint4*)((char*)Bh_sh + (n_ + 32 * j) * 80) + q_) = rH[j];
            *((uint4*)((char*)Bl_sh + (n_ + 32 * j) * 80) + q_) = rL[j];
        }
        __syncthreads();
        if (c + 1 < 16) {
            const uint4* srcH = (const uint4*)(g_B2h + (size_t)(c + 1) * 4096);
            const uint4* srcL = (const uint4*)(g_B2l + (size_t)(c + 1) * 4096);
#pragma unroll
            for (int j = 0; j < 4; j++) {
                rH[j] = srcH[(n_ + 32 * j) * 4 + q_];
                rL[j] = srcL[(n_ + 32 * j) * 4 + q_];
            }
        }

#pragma unroll 2
        for (int ob = 0; ob < 16; ob++) {
            const __nv_bfloat16* bhp = &Bh_sh[(ob * 8 + g) * 40];
            const __nv_bfloat16* blp = &Bl_sh[(ob * 8 + g) * 40];
            uint32_t bh00 = *(const uint32_t*)&bhp[2 * m];
            uint32_t bh01 = *(const uint32_t*)&bhp[2 * m + 8];
            uint32_t bh10 = *(const uint32_t*)&bhp[2 * m + 16];
            uint32_t bh11 = *(const uint32_t*)&bhp[2 * m + 24];
            uint32_t bl00 = *(const uint32_t*)&blp[2 * m];
            uint32_t bl01 = *(const uint32_t*)&blp[2 * m + 8];
            uint32_t bl10 = *(const uint32_t*)&blp[2 * m + 16];
            uint32_t bl11 = *(const uint32_t*)&blp[2 * m + 24];

            float cA0 = 0.f, cA1 = 0.f, cA2 = 0.f, cA3 = 0.f;
            float cB0 = 0.f, cB1 = 0.f, cB2 = 0.f, cB3 = 0.f;
            mma_bf16(cA0, cA1, cA2, cA3, ah[0][0], ah[0][1], ah[0][2], ah[0][3], bh00, bh01);
            mma_bf16(cA0, cA1, cA2, cA3, al[0][0], al[0][1], al[0][2], al[0][3], bh00, bh01);
            mma_bf16(cA0, cA1, cA2, cA3, ah[0][0], ah[0][1], ah[0][2], ah[0][3], bl00, bl01);
            mma_bf16(cB0, cB1, cB2, cB3, ah[1][0], ah[1][1], ah[1][2], ah[1][3], bh10, bh11);
            mma_bf16(cB0, cB1, cB2, cB3, al[1][0], al[1][1], al[1][2], al[1][3], bh10, bh11);
            mma_bf16(cB0, cB1, cB2, cB3, ah[1][0], ah[1][1], ah[1][2], ah[1][3], bl10, bl11);

            int iL = 2 * c + (ob >> 3);
            float xa = x_sh[eA * 33 + iL];
            float xb = x_sh[(eA + 8) * 33 + iL];
            int nb = c * 128 + ob * 8 + 2 * m;
            float bv0 = bias_sh[nb], bv1 = bias_sh[nb + 1];
            int ai = (ob & 7) * 2;
            acc[ai]          = fmaf(xa, lrelu(cA0 + cB0 + bv0), acc[ai]);
            acc[ai + 1]      = fmaf(xa, lrelu(cA1 + cB1 + bv1), acc[ai + 1]);
            acc[16 + ai]     = fmaf(xb, lrelu(cA2 + cB2 + bv0), acc[16 + ai]);
            acc[16 + ai + 1] = fmaf(xb, lrelu(cA3 + cB3 + bv1), acc[16 + ai + 1]);
        }
    }

    int o0 = 2 * m;
    if (e0 + eA < NE) {
        int d = dst_sh[eA];
#pragma unroll
        for (int ob = 0; ob < 8; ob++) {
            atomicAdd(&g_x2[d * 64 + ob * 8 + o0], acc[ob * 2]);
            atomicAdd(&g_x2[d * 64 + ob * 8 + o0 + 1], acc[ob * 2 + 1]);
        }
    }
    if (e0 + eA + 8 < NE) {
        int d = dst_sh[eA + 8];
#pragma unroll
        for (int ob = 0; ob < 8; ob++) {
            atomicAdd(&g_x2[d * 64 + ob * 8 + o0], acc[16 + ob * 2]);
            atomicAdd(&g_x2[d * 64 + ob * 8 + o0 + 1], acc[16 + ob * 2 + 1]);
        }
    }
}

// ---------------- K6a: edge MLP layer1 via warp MMA (2 groups/block) ---------
__global__ __launch_bounds__(128) void k6a_mma(const int* __restrict__ ei,
                                               const float* __restrict__ b1) {
    __shared__ __nv_bfloat16 Ah[16 * 152], Al[16 * 152];
    __shared__ __nv_bfloat16 Bh[64 * 152], Bl[64 * 152];
    __shared__ float sb1[64];
    __shared__ int se[32];
    int tid = threadIdx.x;

    if (tid >= 64 && tid < 128) sb1[tid - 64] = b1[tid - 64];
    {
        const uint4* sH = (const uint4*)g_W1h;
        const uint4* sL = (const uint4*)g_W1l;
        uint4* dH = (uint4*)Bh;
        uint4* dL = (uint4*)Bl;
        for (int i = tid; i < 1216; i += 128) { dH[i] = sH[i]; dL[i] = sL[i]; }
    }

    int lane = tid & 31, w = tid >> 5, g = lane >> 2, m = lane & 3;

#pragma unroll
    for (int grp = 0; grp < 2; grp++) {
        int e0 = (blockIdx.x * 2 + grp) * 16;
        __syncthreads();   // protect A/se reuse (and B/sb1 readiness on grp 0)
        if (tid < 16) se[tid] = ei[e0 + tid];
        else if (tid < 32) se[tid] = ei[NE + e0 + tid - 16];
        __syncthreads();
        for (int i = tid; i < 16 * 152; i += 128) {
            int e = i / 152, k = i - e * 152;
            float v = 0.f;
            if (k < 64)       v = g_x2[se[e] * 64 + k];
            else if (k < 128) v = g_x2[se[16 + e] * 64 + (k - 64)];
            else if (k < 138) v = g_ebn[(e0 + e) * 10 + (k - 128)];
            __nv_bfloat16 bh = __float2bfloat16(v);
            Ah[i] = bh;
            Al[i] = __float2bfloat16(v - __bfloat162float(bh));
        }
        __syncthreads();

#pragma unroll
        for (int ob = 0; ob < 2; ob++) {
            int n0 = (w * 2 + ob) * 8;
            float c0 = 0.f, c1 = 0.f, c2 = 0.f, c3 = 0.f;
#pragma unroll
            for (int ks = 0; ks < 9; ks++) {
                int kb = ks * 16 + 2 * m;
                uint32_t a0 = *(const uint32_t*)&Ah[g * 152 + kb];
                uint32_t a1 = *(const uint32_t*)&Ah[(g + 8) * 152 + kb];
                uint32_t a2 = *(const uint32_t*)&Ah[g * 152 + kb + 8];
                uint32_t a3 = *(const uint32_t*)&Ah[(g + 8) * 152 + kb + 8];
                uint32_t l0 = *(const uint32_t*)&Al[g * 152 + kb];
                uint32_t l1 = *(const uint32_t*)&Al[(g + 8) * 152 + kb];
                uint32_t l2 = *(const uint32_t*)&Al[g * 152 + kb + 8];
                uint32_t l3 = *(const uint32_t*)&Al[(g + 8) * 152 + kb + 8];
                const __nv_bfloat16* bp = &Bh[(n0 + g) * 152 + ks * 16];
                const __nv_bfloat16* lp = &Bl[(n0 + g) * 152 + ks * 16];
                uint32_t b0 = *(const uint32_t*)&bp[2 * m];
                uint32_t b1r = *(const uint32_t*)&bp[2 * m + 8];
                uint32_t bl0 = *(const uint32_t*)&lp[2 * m];
                uint32_t bl1 = *(const uint32_t*)&lp[2 * m + 8];
                mma_bf16(c0, c1, c2, c3, a0, a1, a2, a3, b0, b1r);
                mma_bf16(c0, c1, c2, c3, l0, l1, l2, l3, b0, b1r);
                mma_bf16(c0, c1, c2, c3, a0, a1, a2, a3, bl0, bl1);
            }
            int col = n0 + 2 * m;
            g_m1[(e0 + g) * 64 + col]         = lrelu(c0 + sb1[col]);
            g_m1[(e0 + g) * 64 + col + 1]     = lrelu(c1 + sb1[col + 1]);
            g_m1[(e0 + g + 8) * 64 + col]     = lrelu(c2 + sb1[col]);
            g_m1[(e0 + g + 8) * 64 + col + 1] = lrelu(c3 + sb1[col + 1]);
        }
    }
}

// ---------------- K6b: edge MLP layers 2-5 (parallel tail) -------------------
__global__ __launch_bounds__(256) void k6b_mlp(
    const float* __restrict__ w2, const float* __restrict__ b2,
    const float* __restrict__ w3, const float* __restrict__ b3,
    const float* __restrict__ w4, const float* __restrict__ b4,
    const float* __restrict__ w5, const float* __restrict__ b5,
    float* __restrict__ out) {
    __shared__ float sw2[2048], sw3[512], sw4[128], sw5[16];
    __shared__ float sb2[32], sb3[16], sb4[8], sb5[2];
    __shared__ __align__(16) float h1_sh[64 * 36];
    __shared__ __align__(16) float h2_sh[32 * 36];
    __shared__ float h3_sh[16 * 36];
    __shared__ float h4_sh[8 * 36];
    int tid = threadIdx.x;
    int e0 = blockIdx.x * 32;

    for (int i = tid; i < 2048; i += 256) sw2[i] = w2[i];
    for (int i = tid; i < 512; i += 256) sw3[i] = w3[i];
    if (tid < 128) sw4[tid] = w4[tid];
    if (tid < 16) sw5[tid] = w5[tid];
    if (tid < 32) sb2[tid] = b2[tid];
    if (tid < 16) sb3[tid] = b3[tid];
    if (tid < 8) sb4[tid] = b4[tid];
    if (tid < 2) sb5[tid] = b5[tid];
    for (int i = tid; i < 2048; i += 256) {
        int k = i & 63, e = i >> 6;
        h1_sh[k * 36 + e] = g_m1[(e0 + e) * 64 + k];
    }
    __syncthreads();

    // layer 2: 64 -> 32 (FFMA2)
    {
        int o = tid & 31, g = tid >> 5;
        ull a0 = bcast2(sb2[o]);
        ull a1 = a0;
#pragma unroll 4
        for (int k = 0; k < 64; k++) {
            ull wb = bcast2(sw2[k * 32 + o]);
            ulonglong2 h = *(const ulonglong2*)&h1_sh[k * 36 + g * 4];
            a0 = fma2(h.x, wb, a0);
            a1 = fma2(h.y, wb, a1);
        }
        float2 v0 = unpk2(a0), v1 = unpk2(a1);
        h2_sh[o * 36 + g * 4 + 0] = lrelu(v0.x);
        h2_sh[o * 36 + g * 4 + 1] = lrelu(v0.y);
        h2_sh[o * 36 + g * 4 + 2] = lrelu(v1.x);
        h2_sh[o * 36 + g * 4 + 3] = lrelu(v1.y);
    }
    __syncthreads();

    // layer 3: 32 -> 16, 2 outs/thread (256 thr = 32e x 8)
    {
        int e = tid >> 3, ob = (tid & 7) * 2;
        float a0 = sb3[ob], a1 = sb3[ob + 1];
#pragma unroll 8
        for (int k = 0; k < 32; k++) {
            float h = h2_sh[k * 36 + e];
            a0 += h * sw3[k * 16 + ob];
            a1 += h * sw3[k * 16 + ob + 1];
        }
        h3_sh[ob * 36 + e] = lrelu(a0);
        h3_sh[(ob + 1) * 36 + e] = lrelu(a1);
    }
    __syncthreads();

    // layer 4: 16 -> 8, 1 out/thread
    {
        int e = tid >> 3, o = tid & 7;
        float a = sb4[o];
#pragma unroll
        for (int k = 0; k < 16; k++) a += h3_sh[k * 36 + e] * sw4[k * 8 + o];
        h4_sh[o * 36 + e] = lrelu(a);
    }
    __syncthreads();

    // layer 5: 8 -> 2
    if (tid < 64) {
        int e = tid >> 1, o = tid & 1;
        float a = sb5[o];
#pragma unroll
        for (int k = 0; k < 8; k++) a += h4_sh[k * 36 + e] * sw5[k * 2 + o];
        out[(size_t)(e0 + e) * 2 + o] = a;
    }
}

// ---------------- launch -----------------------------------------------------
extern "C" void kernel_launch(void* const* d_in, const int* in_sizes, int n_in,
                              void* d_out, int out_size) {
    const float* x = (const float*)d_in[0];
    const float* e = (const float*)d_in[1];
    const int* ei = (const int*)d_in[2];
    const float* bn_node_g = (const float*)d_in[4];
    const float* bn_node_b = (const float*)d_in[5];
    const float* bn_edge_g = (const float*)d_in[6];
    const float* bn_edge_b = (const float*)d_in[7];
    const float* nn1_w1 = (const float*)d_in[8];
    const float* nn1_b1 = (const float*)d_in[9];
    const float* nn1_w2 = (const float*)d_in[10];
    const float* nn1_b2 = (const float*)d_in[11];
    const float* nn2_w1 = (const float*)d_in[12];
    const float* nn2_b1 = (const float*)d_in[13];
    const float* nn2_w2 = (const float*)d_in[14];
    const float* nn2_b2 = (const float*)d_in[15];
    const float* l1_root = (const float*)d_in[16];
    const float* l1_bias = (const float*)d_in[17];
    const float* l2_root = (const float*)d_in[18];
    const float* l2_bias = (const float*)d_in[19];
    const float* mlp_w1 = (const float*)d_in[20];
    const float* mlp_b1 = (const float*)d_in[21];
    const float* mlp_w2 = (const float*)d_in[22];
    const float* mlp_b2 = (const float*)d_in[23];
    const float* mlp_w3 = (const float*)d_in[24];
    const float* mlp_b3 = (const float*)d_in[25];
    const float* mlp_w4 = (const float*)d_in[26];
    const float* mlp_b4 = (const float*)d_in[27];
    const float* mlp_w5 = (const float*)d_in[28];
    const float* mlp_b5 = (const float*)d_in[29];
    float* out = (float*)d_out;

    bn_init<<<1, 32>>>();
    bn_acc<<<56, 320>>>(e, x);
    bn_fin<<<1, 32>>>();
    prep_w<<<326, 256>>>(nn1_w2, nn2_w2, mlp_w1);
    k1_edge<<<(NE + 255) / 256, 256>>>(e, bn_edge_g, bn_edge_b, nn1_w1, nn1_b1, nn2_w1, nn2_b1);
    k2_node<<<(NN + 255) / 256, 256>>>(x, bn_node_g, bn_node_b, l1_root, l1_bias);
    k3_mma<<<(NE + 63) / 64, 128>>>(ei, nn1_b2);
    k4_node<<<(NN * 64 + 255) / 256, 256>>>(l2_root, l2_bias);
    k5_conv2_mma<<<(NE + 63) / 64, 128>>>(ei, nn2_b2);
    k6a_mma<<<3125, 128>>>(ei, mlp_b1);
    k6b_mlp<<<NE / 32, 256>>>(mlp_w2, mlp_b2, mlp_w3, mlp_b3,
                              mlp_w4, mlp_b4, mlp_w5, mlp_b5, out);
}

// round 16
// speedup vs baseline: 1.4397x; 1.4397x over previous
#include <cuda_runtime.h>
#include <cuda_bf16.h>
#include <cstdint>

#define NN 20000
#define NE 100000

typedef unsigned long long ull;

__device__ float g_ebn[NE * 10];
__device__ float g_h1[NE * 16];
__device__ float g_h2[NE * 32];
__device__ float g_xbn[NN * 16];
__device__ float g_x1[NN * 32];
__device__ float g_x2[NN * 64];
__device__ float g_m1[NE * 64];            // edge-MLP layer1 activations
__device__ __nv_bfloat16 g_C1h[512 * 16];  // conv1 w2 bf16 hi, [n][k]
__device__ __nv_bfloat16 g_C1l[512 * 16];  // conv1 w2 bf16 lo
__device__ __nv_bfloat16 g_B2h[2048 * 32]; // conv2 w2 bf16 hi, [n][k]
__device__ __nv_bfloat16 g_B2l[2048 * 32]; // conv2 w2 bf16 lo
__device__ __nv_bfloat16 g_W1h[64 * 152];  // mlp_w1 bf16 hi, [n][k pad152]
__device__ __nv_bfloat16 g_W1l[64 * 152];  // mlp_w1 bf16 lo
__device__ double g_dsum[26], g_dss[26];
__device__ float g_emean[10], g_ers[10];
__device__ float g_xmean[16], g_xrs[16];

__device__ __forceinline__ float lrelu(float v) { return v > 0.f ? v : 0.1f * v; }

// ---- packed f32x2 helpers (k6b) ---------------------------------------------
__device__ __forceinline__ ull bcast2(float v) {
    ull r;
    unsigned u = __float_as_uint(v);
    asm("mov.b64 %0, {%1, %2};" : "=l"(r) : "r"(u), "r"(u));
    return r;
}
__device__ __forceinline__ ull fma2(ull a, ull b, ull c) {
    ull d;
    asm("fma.rn.f32x2 %0, %1, %2, %3;" : "=l"(d) : "l"(a), "l"(b), "l"(c));
    return d;
}
__device__ __forceinline__ float2 unpk2(ull v) {
    unsigned lo, hi;
    asm("mov.b64 {%0, %1}, %2;" : "=r"(lo), "=r"(hi) : "l"(v));
    return make_float2(__uint_as_float(lo), __uint_as_float(hi));
}

// ---- warp-level bf16 MMA ----------------------------------------------------
__device__ __forceinline__ void mma_bf16(float& c0, float& c1, float& c2, float& c3,
                                         uint32_t a0, uint32_t a1, uint32_t a2, uint32_t a3,
                                         uint32_t b0, uint32_t b1) {
    asm("mma.sync.aligned.m16n8k16.row.col.f32.bf16.bf16.f32 "
        "{%0,%1,%2,%3}, {%4,%5,%6,%7}, {%8,%9}, {%0,%1,%2,%3};"
        : "+f"(c0), "+f"(c1), "+f"(c2), "+f"(c3)
        : "r"(a0), "r"(a1), "r"(a2), "r"(a3), "r"(b0), "r"(b1));
}

// ---------------- BatchNorm statistics (coalesced) ---------------------------
__global__ void bn_init() {
    int t = threadIdx.x;
    if (t < 26) { g_dsum[t] = 0.0; g_dss[t] = 0.0; }
}

__global__ void bn_acc(const float* __restrict__ e, const float* __restrict__ x) {
    __shared__ double s_sh[320], ss_sh[320];
    int b = blockIdx.x, t = threadIdx.x;
    double s = 0.0, ss = 0.0;
    if (b < 40) {
        int base = b * 25000;
        for (int i = base + t; i < base + 25000; i += 320) {
            float f = e[i];
            s += (double)f; ss += (double)f * f;
        }
    } else {
        int base = (b - 40) * 20000;
        for (int i = base + t; i < base + 20000; i += 320) {
            float f = x[i];
            s += (double)f; ss += (double)f * f;
        }
    }
    s_sh[t] = s; ss_sh[t] = ss;
    __syncthreads();
    if (b < 40) {
        if (t < 10) {
            double a = 0.0, c = 0.0;
            for (int k = t; k < 320; k += 10) { a += s_sh[k]; c += ss_sh[k]; }
            atomicAdd(&g_dsum[t], a);
            atomicAdd(&g_dss[t], c);
        }
    } else {
        if (t < 16) {
            double a = 0.0, c = 0.0;
            for (int k = t; k < 320; k += 16) { a += s_sh[k]; c += ss_sh[k]; }
            atomicAdd(&g_dsum[10 + t], a);
            atomicAdd(&g_dss[10 + t], c);
        }
    }
}

__global__ void bn_fin() {
    int t = threadIdx.x;
    if (t < 10) {
        double m = g_dsum[t] / NE;
        double var = g_dss[t] / NE - m * m;
        g_emean[t] = (float)m;
        g_ers[t] = (float)(1.0 / sqrt(var + 1e-5));
    } else if (t < 26) {
        double m = g_dsum[t] / NN;
        double var = g_dss[t] / NN - m * m;
        g_xmean[t - 10] = (float)m;
        g_xrs[t - 10] = (float)(1.0 / sqrt(var + 1e-5));
    }
}

// ---------------- weight prep ------------------------------------------------
__global__ void prep_w(const float* __restrict__ w1g, const float* __restrict__ w2g,
                       const float* __restrict__ mw1) {
    int b = blockIdx.x;
    if (b < 32) {  // conv1: nn1_w2 [16,512] -> bf16 hi/lo [n512][k16]
        int idx = b * 256 + threadIdx.x;
        int n = idx >> 4, k = idx & 15;
        float f = w1g[k * 512 + n];
        __nv_bfloat16 bh = __float2bfloat16(f);
        g_C1h[idx] = bh;
        g_C1l[idx] = __float2bfloat16(f - __bfloat162float(bh));
    } else if (b < 288) {  // conv2: [k32][n2048] -> bf16 hi/lo [n][k]
        int idx = (b - 32) * 256 + threadIdx.x;
        int k = idx & 31, n = idx >> 5;
        float f = w2g[k * 2048 + n];
        __nv_bfloat16 bh = __float2bfloat16(f);
        __nv_bfloat16 bl = __float2bfloat16(f - __bfloat162float(bh));
        g_B2h[n * 32 + k] = bh;
        g_B2l[n * 32 + k] = bl;
    } else {  // mlp_w1 [138,64] -> bf16 hi/lo [n64][k152 pad-zero]
        int idx = (b - 288) * 256 + threadIdx.x;
        int n = idx / 152, k = idx - n * 152;
        float f = (k < 138) ? mw1[k * 64 + n] : 0.f;
        __nv_bfloat16 bh = __float2bfloat16(f);
        g_W1h[idx] = bh;
        g_W1l[idx] = __float2bfloat16(f - __bfloat162float(bh));
    }
}

// ---------------- K1: edge BN + h1 + h2 (coalesced staging) ------------------
__global__ void k1_edge(const float* __restrict__ e,
                        const float* __restrict__ eg, const float* __restrict__ eb,
                        const float* __restrict__ w1, const float* __restrict__ b1,
                        const float* __restrict__ w2, const float* __restrict__ b2) {
    __shared__ float sw1[160], sw2[320], sb1[16], sb2[32], sg[10], sb[10], sm[10], srs[10];
    __shared__ float in_sh[2560];
    int tid = threadIdx.x;
    int base = blockIdx.x * 2560;
    for (int i = tid; i < 160; i += 256) sw1[i] = w1[i];
    for (int i = tid; i < 320; i += 256) sw2[i] = w2[i];
    if (tid < 16) sb1[tid] = b1[tid];
    if (tid < 32) sb2[tid] = b2[tid];
    if (tid < 10) { sg[tid] = eg[tid]; sb[tid] = eb[tid]; sm[tid] = g_emean[tid]; srs[tid] = g_ers[tid]; }
    for (int i = tid; i < 2560; i += 256) {
        int gi = base + i;
        in_sh[i] = (gi < NE * 10) ? e[gi] : 0.f;
    }
    __syncthreads();
    int eid = blockIdx.x * 256 + tid;
    float ev[10];
    if (eid < NE) {
#pragma unroll
        for (int c = 0; c < 10; c++) {
            float f = (in_sh[tid * 10 + c] - sm[c]) * srs[c] * sg[c] + sb[c];
            ev[c] = f;
        }
#pragma unroll
        for (int o = 0; o < 16; o++) {
            float t = sb1[o];
#pragma unroll
            for (int c = 0; c < 10; c++) t += ev[c] * sw1[c * 16 + o];
            g_h1[eid * 16 + o] = lrelu(t);
        }
#pragma unroll
        for (int o = 0; o < 32; o++) {
            float t = sb2[o];
#pragma unroll
            for (int c = 0; c < 10; c++) t += ev[c] * sw2[c * 32 + o];
            g_h2[eid * 32 + o] = lrelu(t);
        }
    }
    __syncthreads();
    if (eid < NE) {
#pragma unroll
        for (int c = 0; c < 10; c++) in_sh[tid * 10 + c] = ev[c];
    }
    __syncthreads();
    for (int i = tid; i < 2560; i += 256) {
        int gi = base + i;
        if (gi < NE * 10) g_ebn[gi] = in_sh[i];
    }
}

// ---------------- K2: node BN + x1 = xbn @ l1_root + l1_bias -----------------
__global__ void k2_node(const float* __restrict__ x,
                        const float* __restrict__ ng, const float* __restrict__ nb,
                        const float* __restrict__ root, const float* __restrict__ bias) {
    __shared__ float sroot[512], sbias[32], sg[16], sb[16], sm[16], srs[16];
    int tid = threadIdx.x;
    for (int i = tid; i < 512; i += 256) sroot[i] = root[i];
    if (tid < 32) sbias[tid] = bias[tid];
    if (tid < 16) { sg[tid] = ng[tid]; sb[tid] = nb[tid]; sm[tid] = g_xmean[tid]; srs[tid] = g_xrs[tid]; }
    __syncthreads();
    int nid = blockIdx.x * 256 + tid;
    if (nid >= NN) return;
    float xv[16];
#pragma unroll
    for (int i = 0; i < 16; i++) {
        float f = (x[nid * 16 + i] - sm[i]) * srs[i] * sg[i] + sb[i];
        xv[i] = f;
        g_xbn[nid * 16 + i] = f;
    }
#pragma unroll
    for (int o = 0; o < 32; o++) {
        float t = sbias[o];
#pragma unroll
        for (int i = 0; i < 16; i++) t += xv[i] * sroot[i * 32 + o];
        g_x1[nid * 32 + o] = t;
    }
}

// ---------------- K3: NNConv1 via warp MMA (bf16 3-split) --------------------
__global__ __launch_bounds__(128) void k3_mma(const int* __restrict__ ei,
                                              const float* __restrict__ b2) {
    __shared__ __nv_bfloat16 Bh[512 * 16], Bl[512 * 16];
    __shared__ __nv_bfloat16 Ah[64 * 24], Al[64 * 24];
    __shared__ float x_sh[64 * 17];
    __shared__ float bias_sh[512];
    __shared__ int dst_sh[64];
    int tid = threadIdx.x;
    int lane = tid & 31, w = tid >> 5;
    int e0 = blockIdx.x * 64;

    {
        const uint4* sH = (const uint4*)g_C1h;
        const uint4* sL = (const uint4*)g_C1l;
        uint4* dH = (uint4*)Bh;
        uint4* dL = (uint4*)Bl;
        for (int i = tid; i < 1024; i += 128) { dH[i] = sH[i]; dL[i] = sL[i]; }
    }
    for (int i = tid; i < 512; i += 128) bias_sh[i] = b2[i];
    if (tid < 64) {
        int ge = e0 + tid;
        dst_sh[tid] = (ge < NE) ? ei[NE + ge] : 0;
    }
    for (int i = tid; i < 1024; i += 128) {
        int e = i >> 4, k = i & 15;
        int ge = e0 + e;
        float f = (ge < NE) ? g_h1[ge * 16 + k] : 0.f;
        __nv_bfloat16 bh = __float2bfloat16(f);
        Ah[e * 24 + k] = bh;
        Al[e * 24 + k] = __float2bfloat16(f - __bfloat162float(bh));
    }
    for (int i = tid; i < 1024; i += 128) {
        int e = i >> 4, ii = i & 15;
        int ge = e0 + e;
        x_sh[e * 17 + ii] = (ge < NE) ? g_xbn[ei[ge] * 16 + ii] : 0.f;
    }
    __syncthreads();

    int g = lane >> 2, m = lane & 3;
    int eA = w * 16 + g;
    uint32_t a0 = *(const uint32_t*)&Ah[eA * 24 + 2 * m];
    uint32_t a1 = *(const uint32_t*)&Ah[(eA + 8) * 24 + 2 * m];
    uint32_t a2 = *(const uint32_t*)&Ah[eA * 24 + 2 * m + 8];
    uint32_t a3 = *(const uint32_t*)&Ah[(eA + 8) * 24 + 2 * m + 8];
    uint32_t l0 = *(const uint32_t*)&Al[eA * 24 + 2 * m];
    uint32_t l1 = *(const uint32_t*)&Al[(eA + 8) * 24 + 2 * m];
    uint32_t l2 = *(const uint32_t*)&Al[eA * 24 + 2 * m + 8];
    uint32_t l3 = *(const uint32_t*)&Al[(eA + 8) * 24 + 2 * m + 8];

    float acc[16];
#pragma unroll
    for (int i = 0; i < 16; i++) acc[i] = 0.f;

#pragma unroll 4
    for (int ob = 0; ob < 64; ob++) {
        const __nv_bfloat16* bp = &Bh[(ob * 8 + g) * 16];
        const __nv_bfloat16* lp = &Bl[(ob * 8 + g) * 16];
        uint32_t b0 = *(const uint32_t*)&bp[2 * m];
        uint32_t b1 = *(const uint32_t*)&bp[2 * m + 8];
        uint32_t bl0 = *(const uint32_t*)&lp[2 * m];
        uint32_t bl1 = *(const uint32_t*)&lp[2 * m + 8];

        float c0 = 0.f, c1 = 0.f, c2 = 0.f, c3 = 0.f;
        mma_bf16(c0, c1, c2, c3, a0, a1, a2, a3, b0, b1);
        mma_bf16(c0, c1, c2, c3, l0, l1, l2, l3, b0, b1);
        mma_bf16(c0, c1, c2, c3, a0, a1, a2, a3, bl0, bl1);

        int iL = ob >> 2;
        float xa = x_sh[eA * 17 + iL];
        float xb = x_sh[(eA + 8) * 17 + iL];
        float bv0 = bias_sh[ob * 8 + 2 * m];
        float bv1 = bias_sh[ob * 8 + 2 * m + 1];
        int q = (ob & 3) * 2;
        acc[q]         = fmaf(xa, lrelu(c0 + bv0), acc[q]);
        acc[q + 1]     = fmaf(xa, lrelu(c1 + bv1), acc[q + 1]);
        acc[8 + q]     = fmaf(xb, lrelu(c2 + bv0), acc[8 + q]);
        acc[8 + q + 1] = fmaf(xb, lrelu(c3 + bv1), acc[8 + q + 1]);
    }

    int o0 = 2 * m;
    if (e0 + eA < NE) {
        int d = dst_sh[eA];
#pragma unroll
        for (int q = 0; q < 4; q++) {
            atomicAdd(&g_x1[d * 32 + q * 8 + o0], acc[q * 2]);
            atomicAdd(&g_x1[d * 32 + q * 8 + o0 + 1], acc[q * 2 + 1]);
        }
    }
    if (e0 + eA + 8 < NE) {
        int d = dst_sh[eA + 8];
#pragma unroll
        for (int q = 0; q < 4; q++) {
            atomicAdd(&g_x1[d * 32 + q * 8 + o0], acc[8 + q * 2]);
            atomicAdd(&g_x1[d * 32 + q * 8 + o0 + 1], acc[8 + q * 2 + 1]);
        }
    }
}

// ---------------- K4: x2 = x1 @ l2_root + l2_bias ----------------------------
__global__ void k4_node(const float* __restrict__ root, const float* __restrict__ bias) {
    __shared__ float sroot[2048], sbias[64];
    int tid = threadIdx.x;
    for (int i = tid; i < 2048; i += 256) sroot[i] = root[i];
    if (tid < 64) sbias[tid] = bias[tid];
    __syncthreads();
    int idx = blockIdx.x * 256 + tid;
    if (idx >= NN * 64) return;
    int n = idx >> 6, o = idx & 63;
    float t = sbias[o];
#pragma unroll
    for (int i = 0; i < 32; i++) t += g_x1[n * 32 + i] * sroot[i * 64 + o];
    g_x2[idx] = t;
}

// ---------------- K5: NNConv2 via warp MMA (bf16 3-split) --------------------
__global__ __launch_bounds__(128) void k5_conv2_mma(const int* __restrict__ ei,
                                                    const float* __restrict__ b2) {
    __shared__ __nv_bfloat16 Bh_sh[128 * 40];
    __shared__ __nv_bfloat16 Bl_sh[128 * 40];
    __shared__ __nv_bfloat16 Ah_sh[64 * 40];
    __shared__ __nv_bfloat16 Al_sh[64 * 40];
    __shared__ float x_sh[64 * 33];
    __shared__ float bias_sh[2048];
    __shared__ int dst_sh[64];
    int tid = threadIdx.x;
    int lane = tid & 31, w = tid >> 5;
    int e0 = blockIdx.x * 64;

    uint4 rH[4], rL[4];
    int n_ = tid >> 2, q_ = tid & 3;
    {
        const uint4* srcH = (const uint4*)(g_B2h);
        const uint4* srcL = (const uint4*)(g_B2l);
#pragma unroll
        for (int j = 0; j < 4; j++) {
            rH[j] = srcH[(n_ + 32 * j) * 4 + q_];
            rL[j] = srcL[(n_ + 32 * j) * 4 + q_];
        }
    }

    for (int i = tid; i < 2048; i += 128) {
        int e = i >> 5, k = i & 31;
        int ge = e0 + e;
        float f = (ge < NE) ? g_h2[ge * 32 + k] : 0.f;
        __nv_bfloat16 bh = __float2bfloat16(f);
        Ah_sh[e * 40 + k] = bh;
        Al_sh[e * 40 + k] = __float2bfloat16(f - __bfloat162float(bh));
    }
    for (int i = tid; i < 2048; i += 128) {
        int e = i >> 5, ii = i & 31;
        int ge = e0 + e;
        x_sh[e * 33 + ii] = (ge < NE) ? g_x1[ei[ge] * 32 + ii] : 0.f;
    }
    if (tid < 64) {
        int ge = e0 + tid;
        dst_sh[tid] = (ge < NE) ? ei[NE + ge] : 0;
    }
    for (int i = tid; i < 2048; i += 128) bias_sh[i] = b2[i];
    __syncthreads();

    int g = lane >> 2, m = lane & 3;
    int eA = w * 16 + g;
    uint32_t ah[2][4], al[2][4];
#pragma unroll
    for (int ks = 0; ks < 2; ks++) {
        int kb = ks * 16 + 2 * m;
        ah[ks][0] = *(const uint32_t*)&Ah_sh[eA * 40 + kb];
        ah[ks][1] = *(const uint32_t*)&Ah_sh[(eA + 8) * 40 + kb];
        ah[ks][2] = *(const uint32_t*)&Ah_sh[eA * 40 + kb + 8];
        ah[ks][3] = *(const uint32_t*)&Ah_sh[(eA + 8) * 40 + kb + 8];
        al[ks][0] = *(const uint32_t*)&Al_sh[eA * 40 + kb];
        al[ks][1] = *(const uint32_t*)&Al_sh[(eA + 8) * 40 + kb];
        al[ks][2] = *(const uint32_t*)&Al_sh[eA * 40 + kb + 8];
        al[ks][3] = *(const uint32_t*)&Al_sh[(eA + 8) * 40 + kb + 8];
    }

    float acc[32];
#pragma unroll
    for (int i = 0; i < 32; i++) acc[i] = 0.f;

    for (int c = 0; c < 16; c++) {
        if (c > 0) __syncthreads();
#pragma unroll
        for (int j = 0; j < 4; j++) {
            *((uint4*)((char*)Bh_sh + (n_ + 32 * j) * 80) + q_) = rH[j];
            *((uint4*)((char*)Bl_sh + (n_ + 32 * j) * 80) + q_) = rL[j];
        }
        __syncthreads();
        if (c + 1 < 16) {
            const uint4* srcH = (const uint4*)(g_B2h + (size_t)(c + 1) * 4096);
            const uint4* srcL = (const uint4*)(g_B2l + (size_t)(c + 1) * 4096);
#pragma unroll
            for (int j = 0; j < 4; j++) {
                rH[j] = srcH[(n_ + 32 * j) * 4 + q_];
                rL[j] = srcL[(n_ + 32 * j) * 4 + q_];
            }
        }

#pragma unroll 2
        for (int ob = 0; ob < 16; ob++) {
            const __nv_bfloat16* bhp = &Bh_sh[(ob * 8 + g) * 40];
            const __nv_bfloat16* blp = &Bl_sh[(ob * 8 + g) * 40];
            uint32_t bh00 = *(const uint32_t*)&bhp[2 * m];
            uint32_t bh01 = *(const uint32_t*)&bhp[2 * m + 8];
            uint32_t bh10 = *(const uint32_t*)&bhp[2 * m + 16];
            uint32_t bh11 = *(const uint32_t*)&bhp[2 * m + 24];
            uint32_t bl00 = *(const uint32_t*)&blp[2 * m];
            uint32_t bl01 = *(const uint32_t*)&blp[2 * m + 8];
            uint32_t bl10 = *(const uint32_t*)&blp[2 * m + 16];
            uint32_t bl11 = *(const uint32_t*)&blp[2 * m + 24];

            float cA0 = 0.f, cA1 = 0.f, cA2 = 0.f, cA3 = 0.f;
            float cB0 = 0.f, cB1 = 0.f, cB2 = 0.f, cB3 = 0.f;
            mma_bf16(cA0, cA1, cA2, cA3, ah[0][0], ah[0][1], ah[0][2], ah[0][3], bh00, bh01);
            mma_bf16(cA0, cA1, cA2, cA3, al[0][0], al[0][1], al[0][2], al[0][3], bh00, bh01);
            mma_bf16(cA0, cA1, cA2, cA3, ah[0][0], ah[0][1], ah[0][2], ah[0][3], bl00, bl01);
            mma_bf16(cB0, cB1, cB2, cB3, ah[1][0], ah[1][1], ah[1][2], ah[1][3], bh10, bh11);
            mma_bf16(cB0, cB1, cB2, cB3, al[1][0], al[1][1], al[1][2], al[1][3], bh10, bh11);
            mma_bf16(cB0, cB1, cB2, cB3, ah[1][0], ah[1][1], ah[1][2], ah[1][3], bl10, bl11);

            int iL = 2 * c + (ob >> 3);
            float xa = x_sh[eA * 33 + iL];
            float xb = x_sh[(eA + 8) * 33 + iL];
            int nb = c * 128 + ob * 8 + 2 * m;
            float bv0 = bias_sh[nb], bv1 = bias_sh[nb + 1];
            int ai = (ob & 7) * 2;
            acc[ai]          = fmaf(xa, lrelu(cA0 + cB0 + bv0), acc[ai]);
            acc[ai + 1]      = fmaf(xa, lrelu(cA1 + cB1 + bv1), acc[ai + 1]);
            acc[16 + ai]     = fmaf(xb, lrelu(cA2 + cB2 + bv0), acc[16 + ai]);
            acc[16 + ai + 1] = fmaf(xb, lrelu(cA3 + cB3 + bv1), acc[16 + ai + 1]);
        }
    }

    int o0 = 2 * m;
    if (e0 + eA < NE) {
        int d = dst_sh[eA];
#pragma unroll
        for (int ob = 0; ob < 8; ob++) {
            atomicAdd(&g_x2[d * 64 + ob * 8 + o0], acc[ob * 2]);
            atomicAdd(&g_x2[d * 64 + ob * 8 + o0 + 1], acc[ob * 2 + 1]);
        }
    }
    if (e0 + eA + 8 < NE) {
        int d = dst_sh[eA + 8];
#pragma unroll
        for (int ob = 0; ob < 8; ob++) {
            atomicAdd(&g_x2[d * 64 + ob * 8 + o0], acc[16 + ob * 2]);
            atomicAdd(&g_x2[d * 64 + ob * 8 + o0 + 1], acc[16 + ob * 2 + 1]);
        }
    }
}

// ---------------- K6a: edge MLP layer1 via warp MMA (bf16 3-split) -----------
__global__ __launch_bounds__(128) void k6a_mma(const int* __restrict__ ei,
                                               const float* __restrict__ b1) {
    __shared__ __nv_bfloat16 Ah[16 * 152], Al[16 * 152];
    __shared__ __nv_bfloat16 Bh[64 * 152], Bl[64 * 152];
    __shared__ float sb1[64];
    __shared__ int se[32];
    int tid = threadIdx.x;
    int e0 = blockIdx.x * 16;

    if (tid < 16) se[tid] = ei[e0 + tid];
    else if (tid < 32) se[tid] = ei[NE + e0 + tid - 16];
    if (tid >= 64 && tid < 128) sb1[tid - 64] = b1[tid - 64];
    {
        const uint4* sH = (const uint4*)g_W1h;
        const uint4* sL = (const uint4*)g_W1l;
        uint4* dH = (uint4*)Bh;
        uint4* dL = (uint4*)Bl;
        for (int i = tid; i < 1216; i += 128) { dH[i] = sH[i]; dL[i] = sL[i]; }
    }
    __syncthreads();

    for (int i = tid; i < 16 * 152; i += 128) {
        int e = i / 152, k = i - e * 152;
        float v = 0.f;
        if (k < 64)       v = g_x2[se[e] * 64 + k];
        else if (k < 128) v = g_x2[se[16 + e] * 64 + (k - 64)];
        else if (k < 138) v = g_ebn[(e0 + e) * 10 + (k - 128)];
        __nv_bfloat16 bh = __float2bfloat16(v);
        Ah[i] = bh;
        Al[i] = __float2bfloat16(v - __bfloat162float(bh));
    }
    __syncthreads();

    int lane = tid & 31, w = tid >> 5, g = lane >> 2, m = lane & 3;
#pragma unroll
    for (int ob = 0; ob < 2; ob++) {
        int n0 = (w * 2 + ob) * 8;
        float c0 = 0.f, c1 = 0.f, c2 = 0.f, c3 = 0.f;
#pragma unroll
        for (int ks = 0; ks < 9; ks++) {
            int kb = ks * 16 + 2 * m;
            uint32_t a0 = *(const uint32_t*)&Ah[g * 152 + kb];
            uint32_t a1 = *(const uint32_t*)&Ah[(g + 8) * 152 + kb];
            uint32_t a2 = *(const uint32_t*)&Ah[g * 152 + kb + 8];
            uint32_t a3 = *(const uint32_t*)&Ah[(g + 8) * 152 + kb + 8];
            uint32_t l0 = *(const uint32_t*)&Al[g * 152 + kb];
            uint32_t l1 = *(const uint32_t*)&Al[(g + 8) * 152 + kb];
            uint32_t l2 = *(const uint32_t*)&Al[g * 152 + kb + 8];
            uint32_t l3 = *(const uint32_t*)&Al[(g + 8) * 152 + kb + 8];
            const __nv_bfloat16* bp = &Bh[(n0 + g) * 152 + ks * 16];
            const __nv_bfloat16* lp = &Bl[(n0 + g) * 152 + ks * 16];
            uint32_t b0 = *(const uint32_t*)&bp[2 * m];
            uint32_t b1r = *(const uint32_t*)&bp[2 * m + 8];
            uint32_t bl0 = *(const uint32_t*)&lp[2 * m];
            uint32_t bl1 = *(const uint32_t*)&lp[2 * m + 8];
            mma_bf16(c0, c1, c2, c3, a0, a1, a2, a3, b0, b1r);
            mma_bf16(c0, c1, c2, c3, l0, l1, l2, l3, b0, b1r);
            mma_bf16(c0, c1, c2, c3, a0, a1, a2, a3, bl0, bl1);
        }
        int col = n0 + 2 * m;
        g_m1[(e0 + g) * 64 + col]         = lrelu(c0 + sb1[col]);
        g_m1[(e0 + g) * 64 + col + 1]     = lrelu(c1 + sb1[col + 1]);
        g_m1[(e0 + g + 8) * 64 + col]     = lrelu(c2 + sb1[col]);
        g_m1[(e0 + g + 8) * 64 + col + 1] = lrelu(c3 + sb1[col + 1]);
    }
}

// ---------------- K6b: edge MLP layers 2-5 -----------------------------------
__global__ __launch_bounds__(256) void k6b_mlp(
    const float* __restrict__ w2, const float* __restrict__ b2,
    const float* __restrict__ w3, const float* __restrict__ b3,
    const float* __restrict__ w4, const float* __restrict__ b4,
    const float* __restrict__ w5, const float* __restrict__ b5,
    float* __restrict__ out) {
    __shared__ float sw2[2048], sw3[512], sw4[128], sw5[16];
    __shared__ float sb2[32], sb3[16], sb4[8], sb5[2];
    __shared__ __align__(16) float h1_sh[64 * 36];
    __shared__ __align__(16) float h2_sh[32 * 36];
    int tid = threadIdx.x;
    int e0 = blockIdx.x * 32;

    for (int i = tid; i < 2048; i += 256) sw2[i] = w2[i];
    for (int i = tid; i < 512; i += 256) sw3[i] = w3[i];
    if (tid < 128) sw4[tid] = w4[tid];
    if (tid < 16) sw5[tid] = w5[tid];
    if (tid < 32) sb2[tid] = b2[tid];
    if (tid < 16) sb3[tid] = b3[tid];
    if (tid < 8) sb4[tid] = b4[tid];
    if (tid < 2) sb5[tid] = b5[tid];
    for (int i = tid; i < 2048; i += 256) {
        int k = i & 63, e = i >> 6;
        h1_sh[k * 36 + e] = g_m1[(e0 + e) * 64 + k];
    }
    __syncthreads();

    {
        int o = tid & 31, g = tid >> 5;
        ull a0 = bcast2(sb2[o]);
        ull a1 = a0;
#pragma unroll 4
        for (int k = 0; k < 64; k++) {
            ull wb = bcast2(sw2[k * 32 + o]);
            ulonglong2 h = *(const ulonglong2*)&h1_sh[k * 36 + g * 4];
            a0 = fma2(h.x, wb, a0);
            a1 = fma2(h.y, wb, a1);
        }
        float2 v0 = unpk2(a0), v1 = unpk2(a1);
        h2_sh[o * 36 + g * 4 + 0] = lrelu(v0.x);
        h2_sh[o * 36 + g * 4 + 1] = lrelu(v0.y);
        h2_sh[o * 36 + g * 4 + 2] = lrelu(v1.x);
        h2_sh[o * 36 + g * 4 + 3] = lrelu(v1.y);
    }
    __syncthreads();

    if (tid < 32) {
        int e = tid, ge = e0 + e;
        float h2r[32];
#pragma unroll
        for (int k = 0; k < 32; k++) h2r[k] = h2_sh[k * 36 + e];
        float h3[16];
#pragma unroll
        for (int o = 0; o < 16; o++) {
            float a = sb3[o];
#pragma unroll
            for (int k = 0; k < 32; k++) a += h2r[k] * sw3[k * 16 + o];
            h3[o] = lrelu(a);
        }
        float h4[8];
#pragma unroll
        for (int o = 0; o < 8; o++) {
            float a = sb4[o];
#pragma unroll
            for (int k = 0; k < 16; k++) a += h3[k] * sw4[k * 8 + o];
            h4[o] = lrelu(a);
        }
#pragma unroll
        for (int o = 0; o < 2; o++) {
            float a = sb5[o];
#pragma unroll
            for (int k = 0; k < 8; k++) a += h4[k] * sw5[k * 2 + o];
            out[(size_t)ge * 2 + o] = a;
        }
    }
}

// ---------------- launch -----------------------------------------------------
extern "C" void kernel_launch(void* const* d_in, const int* in_sizes, int n_in,
                              void* d_out, int out_size) {
    const float* x = (const float*)d_in[0];
    const float* e = (const float*)d_in[1];
    const int* ei = (const int*)d_in[2];
    const float* bn_node_g = (const float*)d_in[4];
    const float* bn_node_b = (const float*)d_in[5];
    const float* bn_edge_g = (const float*)d_in[6];
    const float* bn_edge_b = (const float*)d_in[7];
    const float* nn1_w1 = (const float*)d_in[8];
    const float* nn1_b1 = (const float*)d_in[9];
    const float* nn1_w2 = (const float*)d_in[10];
    const float* nn1_b2 = (const float*)d_in[11];
    const float* nn2_w1 = (const float*)d_in[12];
    const float* nn2_b1 = (const float*)d_in[13];
    const float* nn2_w2 = (const float*)d_in[14];
    const float* nn2_b2 = (const float*)d_in[15];
    const float* l1_root = (const float*)d_in[16];
    const float* l1_bias = (const float*)d_in[17];
    const float* l2_root = (const float*)d_in[18];
    const float* l2_bias = (const float*)d_in[19];
    const float* mlp_w1 = (const float*)d_in[20];
    const float* mlp_b1 = (const float*)d_in[21];
    const float* mlp_w2 = (const float*)d_in[22];
    const float* mlp_b2 = (const float*)d_in[23];
    const float* mlp_w3 = (const float*)d_in[24];
    const float* mlp_b3 = (const float*)d_in[25];
    const float* mlp_w4 = (const float*)d_in[26];
    const float* mlp_b4 = (const float*)d_in[27];
    const float* mlp_w5 = (const float*)d_in[28];
    const float* mlp_b5 = (const float*)d_in[29];
    float* out = (float*)d_out;

    bn_init<<<1, 32>>>();
    bn_acc<<<56, 320>>>(e, x);
    bn_fin<<<1, 32>>>();
    prep_w<<<326, 256>>>(nn1_w2, nn2_w2, mlp_w1);
    k1_edge<<<(NE + 255) / 256, 256>>>(e, bn_edge_g, bn_edge_b, nn1_w1, nn1_b1, nn2_w1, nn2_b1);
    k2_node<<<(NN + 255) / 256, 256>>>(x, bn_node_g, bn_node_b, l1_root, l1_bias);
    k3_mma<<<(NE + 63) / 64, 128>>>(ei, nn1_b2);
    k4_node<<<(NN * 64 + 255) / 256, 256>>>(l2_root, l2_bias);
    k5_conv2_mma<<<(NE + 63) / 64, 128>>>(ei, nn2_b2);
    k6a_mma<<<NE / 16, 128>>>(ei, mlp_b1);
    k6b_mlp<<<NE / 32, 256>>>(mlp_w2, mlp_b2, mlp_w3, mlp_b3,
                              mlp_w4, mlp_b4, mlp_w5, mlp_b5, out);
}